// round 5
// baseline (speedup 1.0000x reference)
#include <cuda_runtime.h>

#define BLK 256

// SMEM layout (floats):
//  x1s : [24][11][16]   @ 0      (4224)
//  x2s : [24][11][16]   @ 4224   (4224)
//  Ws  : [32][36]       @ 8448   (1152)
//  cgs2: ull[1331] dup  @ 9600   (2662 floats)
//  cats: [32][N][16]    @ 12262  (5632 floats max @ N=11)
#define SMEM_FLOATS 17894
#define SMEM_BYTES (SMEM_FLOATS * 4)

typedef unsigned long long ull;

__device__ __forceinline__ ull pack2(float v) {
    ull r; asm("mov.b64 %0, {%1, %1};" : "=l"(r) : "f"(v)); return r;
}
__device__ __forceinline__ ull mul2(ull a, ull b) {
    ull r; asm("mul.rn.f32x2 %0, %1, %2;" : "=l"(r) : "l"(a), "l"(b)); return r;
}
__device__ __forceinline__ ull fma2(ull a, ull b, ull c) {
    ull r; asm("fma.rn.f32x2 %0, %1, %2, %3;" : "=l"(r) : "l"(a), "l"(b), "l"(c)); return r;
}
__device__ __forceinline__ void unpack2(ull v, float& lo, float& hi) {
    asm("mov.b64 {%0, %1}, %2;" : "=f"(lo), "=f"(hi) : "l"(v));
}

__device__ __forceinline__ const float* pick6(
    const float* a0, const float* a1, const float* a2,
    const float* a3, const float* a4, const float* a5, int l) {
    switch (l) {
        case 0: return a0; case 1: return a1; case 2: return a2;
        case 3: return a3; case 4: return a4; default: return a5;
    }
}

template <int N, int CB>
__device__ __forceinline__ void run_pair(
    const float* __restrict__ x1s, const float* __restrict__ x2s,
    const ull* __restrict__ cgs2, float* __restrict__ Ws, ull* __restrict__ cats64,
    const float* __restrict__ Wl, int KIN, int koff,
    float* __restrict__ out, int b0, int moff)
{
    const int tid = threadIdx.x;
    const int bp = tid & 7;          // batch pair 0..7 (f32x2)
    const int hg = (tid >> 3) & 7;   // h quad: h = hg*4 + j
    const int ms = tid >> 6;         // m slice 0..3: mi = ms + 4*mj
    const int rr = tid >> 3;         // 0..31: k row (cat build) / h row (W load)

    constexpr int MS = (N + 3) / 4;
    ull acc[4][MS];
#pragma unroll
    for (int j = 0; j < 4; ++j)
#pragma unroll
        for (int mj = 0; mj < MS; ++mj) acc[j][mj] = 0ull;

    const ull* __restrict__ x1s64 = (const ull*)x1s;
    const ull* __restrict__ x2s64 = (const ull*)x2s;

#pragma unroll 1
    for (int cc = 0; cc < 18; ++cc) {
        // --- W chunk: Wl[h=rr][koff+cc*32+bp*4 ..+3] -> Ws[k*36+h] (R2 style) ---
        {
            const float4 wv = *reinterpret_cast<const float4*>(
                Wl + rr * KIN + koff + cc * 32 + bp * 4);
            float* wp = Ws + (bp * 4) * 36 + rr;
            wp[0]   = wv.x;
            wp[36]  = wv.y;
            wp[72]  = wv.z;
            wp[108] = wv.w;
        }
        // --- cat build: thread owns kk=rr (one (c,d)), all N mi, batch pair bp ---
        {
            const int kg = cc * 32 + rr;
            const int c  = kg / 24;
            const int d  = kg - c * 24;
            const ull* __restrict__ x1p = x1s64 + c * 88 + bp;
            const ull* __restrict__ x2p = x2s64 + d * 88 + bp;
            // cache x2 in registers (static indices); x1 via LDS (ptxas CSEs)
            ull x2r[11];
#pragma unroll
            for (int i = 0; i < 11; ++i) x2r[i] = x2p[i * 8];
            ull* __restrict__ cro = cats64 + rr * (8 * N) + bp;
#pragma unroll
            for (int mi = 0; mi < N; ++mi) {
                constexpr_helper:;
                const int base = mi + CB;     // compile-time in unrolled iter
                ull v = 0ull;
#pragma unroll
                for (int m1i = 0; m1i < 11; ++m1i) {
                    const int m2i = base - m1i;   // compile-time
                    if (m2i >= 0 && m2i < 11) {   // folds at compile time
                        v = fma2(cgs2[mi * 121 + m1i * 11 + m2i],
                                 mul2(x1p[m1i * 8], x2r[m2i]), v);
                    }
                }
                cro[mi * 8] = v;
            }
        }
        __syncthreads();
        // --- GEMM (R2 exact): acc[h=hg*4+j][mi=ms+4mj] += W[h,k]*cat[k,mi,bp] ---
#pragma unroll 4
        for (int k = 0; k < 32; ++k) {
            const float4 w = *reinterpret_cast<const float4*>(&Ws[k * 36 + hg * 4]);
            const ull w2[4] = { pack2(w.x), pack2(w.y), pack2(w.z), pack2(w.w) };
            const ull* __restrict__ cp = cats64 + k * (8 * N) + bp;
#pragma unroll
            for (int mj = 0; mj < MS; ++mj) {
                const int mi = ms + 4 * mj;
                if (mi < N) {                      // warp-uniform
                    const ull cv = cp[mi * 8];
                    acc[0][mj] = fma2(w2[0], cv, acc[0][mj]);
                    acc[1][mj] = fma2(w2[1], cv, acc[1][mj]);
                    acc[2][mj] = fma2(w2[2], cv, acc[2][mj]);
                    acc[3][mj] = fma2(w2[3], cv, acc[3][mj]);
                }
            }
        }
        __syncthreads();
    }

    // --- writeback: batches b0+2bp, b0+2bp+1 ---
    float* op = out + ((b0 + bp * 2) * 32 + hg * 4) * 36 + moff;
#pragma unroll
    for (int j = 0; j < 4; ++j) {
#pragma unroll
        for (int mj = 0; mj < MS; ++mj) {
            const int mi = ms + 4 * mj;
            if (mi < N) {
                float lo, hi;
                unpack2(acc[j][mj], lo, hi);
                atomicAdd(op + j * 36 + mi, lo);
                atomicAdd(op + 32 * 36 + j * 36 + mi, hi);
            }
        }
    }
}

__global__ void __launch_bounds__(BLK, 3) cg_main(
    const float* __restrict__ X0, const float* __restrict__ X1, const float* __restrict__ X2,
    const float* __restrict__ X3, const float* __restrict__ X4, const float* __restrict__ X5,
    const float* __restrict__ W0, const float* __restrict__ W1, const float* __restrict__ W2,
    const float* __restrict__ W3, const float* __restrict__ W4, const float* __restrict__ W5,
    const float* __restrict__ cg, float* __restrict__ out)
{
    extern __shared__ float sm[];
    float* x1s  = sm;
    float* x2s  = sm + 4224;
    float* Ws   = sm + 8448;
    ull*   cgs2 = (ull*)(sm + 9600);
    ull*   cats = (ull*)(sm + 12262);

    const int item = blockIdx.x >> 4;          // 0..110 (l, pair)
    const int b0   = (blockIdx.x & 15) << 4;   // batch tile start

    // decode work item: l ordered 5,4,3,2,1,0 (big work first)
    int l = 0, l1 = 0, l2 = 0, pidx = 0;
    {
        int cur = 0;
        bool done = false;
        for (int oi = 0; oi < 6 && !done; ++oi) {
            int L = 5 - oi;
            int pi = 0;
            for (int a = 0; a <= 5 && !done; ++a) {
                for (int b2 = 0; b2 <= 5; ++b2) {
                    int dd = a - b2; if (dd < 0) dd = -dd;
                    if (dd <= L && L <= a + b2) {
                        if (cur == item) { l = L; l1 = a; l2 = b2; pidx = pi; done = true; break; }
                        ++cur; ++pi;
                    }
                }
            }
        }
    }

    const int n1 = 2 * l1 + 1, n2 = 2 * l2 + 1, n = 2 * l + 1;
    int KIN, moff;
    switch (l) {
        case 0: KIN = 3456;  moff = 0;  break;
        case 1: KIN = 8640;  moff = 1;  break;
        case 2: KIN = 12096; moff = 4;  break;
        case 3: KIN = 13824; moff = 9;  break;
        case 4: KIN = 13824; moff = 16; break;
        default: KIN = 12096; moff = 25; break;
    }
    const float* Xa = pick6(X0, X1, X2, X3, X4, X5, l1);
    const float* Xb = pick6(X0, X1, X2, X3, X4, X5, l2);
    const float* Wl = pick6(W0, W1, W2, W3, W4, W5, l);
    const int koff = pidx * 576;
    const int tid = threadIdx.x;

    // zero-init x tiles (unwritten (c,m) slots must be 0.0, not stale bits)
    for (int i = tid; i < 8448; i += BLK) sm[i] = 0.f;
    __syncthreads();

    // load x tiles: global (b,c,m) -> smem [c][m][b16]
    for (int i = tid; i < 16 * 24 * n1; i += BLK) {
        int b = i / (24 * n1);
        int r = i - b * 24 * n1;
        int c = r / n1;
        int m1 = r - c * n1;
        x1s[(c * 11 + m1) * 16 + b] = Xa[(b0 + b) * 24 * n1 + r];
    }
    for (int i = tid; i < 16 * 24 * n2; i += BLK) {
        int b = i / (24 * n2);
        int r = i - b * 24 * n2;
        int c = r / n2;
        int m2 = r - c * n2;
        x2s[(c * 11 + m2) * 16 + b] = Xb[(b0 + b) * 24 * n2 + r];
    }
    // cg slab, duplicated to both f32x2 lanes (zeros preserved)
    const float* cgp = cg + ((l1 * 6 + l2) * 6 + l) * 1331;
    for (int i = tid; i < n * 121; i += BLK) cgs2[i] = pack2(cgp[i]);
    __syncthreads();

    const int cbase = l1 + l2 - l;
#define RP(Nv, CBv) run_pair<Nv, CBv>(x1s, x2s, cgs2, Ws, cats, Wl, KIN, koff, out, b0, moff)
    switch (l) {
        case 5:
            switch (cbase) {
                case 0: RP(11,0); break; case 1: RP(11,1); break; case 2: RP(11,2); break;
                case 3: RP(11,3); break; case 4: RP(11,4); break; default: RP(11,5); break;
            } break;
        case 4:
            switch (cbase) {
                case 0: RP(9,0); break; case 1: RP(9,1); break; case 2: RP(9,2); break;
                case 3: RP(9,3); break; case 4: RP(9,4); break; case 5: RP(9,5); break;
                default: RP(9,6); break;
            } break;
        case 3:
            switch (cbase) {
                case 0: RP(7,0); break; case 1: RP(7,1); break; case 2: RP(7,2); break;
                case 3: RP(7,3); break; case 4: RP(7,4); break; case 5: RP(7,5); break;
                case 6: RP(7,6); break; default: RP(7,7); break;
            } break;
        case 2:
            switch (cbase) {
                case 0: RP(5,0); break; case 1: RP(5,1); break; case 2: RP(5,2); break;
                case 3: RP(5,3); break; case 4: RP(5,4); break; case 5: RP(5,5); break;
                case 6: RP(5,6); break; case 7: RP(5,7); break; default: RP(5,8); break;
            } break;
        case 1:
            switch (cbase) {
                case 0: RP(3,0); break; case 1: RP(3,1); break; case 2: RP(3,2); break;
                case 3: RP(3,3); break; case 4: RP(3,4); break; case 5: RP(3,5); break;
                case 6: RP(3,6); break; case 7: RP(3,7); break; case 8: RP(3,8); break;
                default: RP(3,9); break;
            } break;
        default:
            switch (cbase) {
                case 0: RP(1,0); break; case 2: RP(1,2); break; case 4: RP(1,4); break;
                case 6: RP(1,6); break; case 8: RP(1,8); break; default: RP(1,10); break;
            } break;
    }
#undef RP
}

__global__ void zero_out_kernel(float* __restrict__ o, int nTot) {
    int i = blockIdx.x * 256 + threadIdx.x;
    if (i < nTot) o[i] = 0.f;
}

extern "C" void kernel_launch(void* const* d_in, const int* in_sizes, int n_in,
                              void* d_out, int out_size)
{
    const float* X[6];
    const float* W[6];
    for (int i = 0; i < 6; ++i) X[i] = (const float*)d_in[i];
    for (int i = 0; i < 6; ++i) W[i] = (const float*)d_in[6 + i];
    const float* cg = (const float*)d_in[12];
    float* out = (float*)d_out;

    const int nTot = 256 * 32 * 36;  // 294912
    zero_out_kernel<<<(nTot + 255) / 256, 256>>>(out, nTot);

    cudaFuncSetAttribute(cg_main, cudaFuncAttributeMaxDynamicSharedMemorySize, SMEM_BYTES);
    cg_main<<<111 * 16, BLK, SMEM_BYTES>>>(
        X[0], X[1], X[2], X[3], X[4], X[5],
        W[0], W[1], W[2], W[3], W[4], W[5],
        cg, out);
}

// round 6
// speedup vs baseline: 1.1828x; 1.1828x over previous
#include <cuda_runtime.h>

#define BLK 256
#define CHUNK 16
#define NCHUNK 36

// SMEM layout (floats):
//  x1s : [24][11][16]   @ 0      (4224)
//  x2s : [24][11][16]   @ 4224   (4224)
//  cgs : [11][11][11]   @ 8448   (1331, padded to 1332)
//  Ws  : [16][36]       @ 9780   (576)   (h stride 36 -> float4-aligned)
//  cats: [16][N][16]    @ 10356  (2816 max @ N=11)
#define SMEM_FLOATS 13172
#define SMEM_BYTES (SMEM_FLOATS * 4)

typedef unsigned long long ull;

__device__ __forceinline__ ull pack2(float v) {
    ull r; asm("mov.b64 %0, {%1, %1};" : "=l"(r) : "f"(v)); return r;
}
__device__ __forceinline__ ull mul2(ull a, ull b) {
    ull r; asm("mul.rn.f32x2 %0, %1, %2;" : "=l"(r) : "l"(a), "l"(b)); return r;
}
__device__ __forceinline__ ull fma2(ull a, ull b, ull c) {
    ull r; asm("fma.rn.f32x2 %0, %1, %2, %3;" : "=l"(r) : "l"(a), "l"(b), "l"(c)); return r;
}
__device__ __forceinline__ void unpack2(ull v, float& lo, float& hi) {
    asm("mov.b64 {%0, %1}, %2;" : "=f"(lo), "=f"(hi) : "l"(v));
}

__device__ __forceinline__ const float* pick6(
    const float* a0, const float* a1, const float* a2,
    const float* a3, const float* a4, const float* a5, int l) {
    switch (l) {
        case 0: return a0; case 1: return a1; case 2: return a2;
        case 3: return a3; case 4: return a4; default: return a5;
    }
}

template <int N>
__device__ __forceinline__ void run_pair(
    const float* __restrict__ x1s, const float* __restrict__ x2s,
    const float* __restrict__ cgs, float* __restrict__ Ws, ull* __restrict__ cats64,
    const float* __restrict__ Wl, int KIN, int koff,
    int n1, int n2, int cbase,
    float* __restrict__ out, int b0, int moff)
{
    const int tid = threadIdx.x;
    const int bp = tid & 7;          // batch pair 0..7 (f32x2)
    const int hg = (tid >> 3) & 7;   // h quad: h = hg*4 + j
    const int ms = tid >> 6;         // m slice 0..3: mi = ms + 4*mj
    const int rr = tid >> 3;         // 0..31: row cursor (cat build) / h (W load)

    constexpr int MS = (N + 3) / 4;
    ull acc[4][MS];
#pragma unroll
    for (int j = 0; j < 4; ++j)
#pragma unroll
        for (int mj = 0; mj < MS; ++mj) acc[j][mj] = 0ull;

    const ull* __restrict__ x1s64 = (const ull*)x1s;
    const ull* __restrict__ x2s64 = (const ull*)x2s;

#pragma unroll 1
    for (int cc = 0; cc < NCHUNK; ++cc) {
        // --- W chunk: Wl[h=rr][koff+cc*16+bp*2 ..+1] -> Ws[k*36+h] ---
        {
            const float2 wv = *reinterpret_cast<const float2*>(
                Wl + rr * KIN + koff + cc * CHUNK + bp * 2);
            float* wp = Ws + (bp * 2) * 36 + rr;
            wp[0]  = wv.x;
            wp[36] = wv.y;
        }
        // --- cat build (R2 style): rows = kk*N + mi, strided by 32 ---
#pragma unroll 1
        for (int row = rr; row < CHUNK * N; row += 32) {
            const int kk = row / N;               // compile-time divisor
            const int mi = row - kk * N;
            const int kg = cc * CHUNK + kk;
            const int c  = kg / 24;
            const int d  = kg - c * 24;
            const ull* __restrict__ x1p = x1s64 + c * 88 + bp;
            const ull* __restrict__ x2p = x2s64 + d * 88 + bp;
            const float* __restrict__ cgrow = cgs + mi * 121;
            const int base = mi + cbase;          // m2i = base - m1i
            ull v = 0ull;
#pragma unroll
            for (int m1i = 0; m1i < 11; ++m1i) {
                if (m1i >= n1) break;             // uniform across CTA
                const int m2i = base - m1i;
                if ((unsigned)m2i < (unsigned)n2) {
                    const ull cg2 = pack2(cgrow[m1i * 11 + m2i]);
                    const ull p   = mul2(x1p[m1i * 8], x2p[m2i * 8]);
                    v = fma2(cg2, p, v);
                }
            }
            cats64[row * 8 + bp] = v;
        }
        __syncthreads();
        // --- GEMM (R2 exact, k<16): acc[h=hg*4+j][mi=ms+4mj] += W[h,k]*cat[k,mi,bp] ---
#pragma unroll 4
        for (int k = 0; k < CHUNK; ++k) {
            const float4 w = *reinterpret_cast<const float4*>(&Ws[k * 36 + hg * 4]);
            const ull w2[4] = { pack2(w.x), pack2(w.y), pack2(w.z), pack2(w.w) };
            const ull* __restrict__ cp = cats64 + k * (8 * N) + bp;
#pragma unroll
            for (int mj = 0; mj < MS; ++mj) {
                const int mi = ms + 4 * mj;
                if (mi < N) {                      // warp-uniform
                    const ull cv = cp[mi * 8];
                    acc[0][mj] = fma2(w2[0], cv, acc[0][mj]);
                    acc[1][mj] = fma2(w2[1], cv, acc[1][mj]);
                    acc[2][mj] = fma2(w2[2], cv, acc[2][mj]);
                    acc[3][mj] = fma2(w2[3], cv, acc[3][mj]);
                }
            }
        }
        __syncthreads();
    }

    // --- writeback: batches b0+2bp, b0+2bp+1 ---
    float* op = out + ((b0 + bp * 2) * 32 + hg * 4) * 36 + moff;
#pragma unroll
    for (int j = 0; j < 4; ++j) {
#pragma unroll
        for (int mj = 0; mj < MS; ++mj) {
            const int mi = ms + 4 * mj;
            if (mi < N) {
                float lo, hi;
                unpack2(acc[j][mj], lo, hi);
                atomicAdd(op + j * 36 + mi, lo);
                atomicAdd(op + 32 * 36 + j * 36 + mi, hi);
            }
        }
    }
}

__global__ void __launch_bounds__(BLK, 4) cg_main(
    const float* __restrict__ X0, const float* __restrict__ X1, const float* __restrict__ X2,
    const float* __restrict__ X3, const float* __restrict__ X4, const float* __restrict__ X5,
    const float* __restrict__ W0, const float* __restrict__ W1, const float* __restrict__ W2,
    const float* __restrict__ W3, const float* __restrict__ W4, const float* __restrict__ W5,
    const float* __restrict__ cg, float* __restrict__ out)
{
    extern __shared__ float sm[];
    float* x1s  = sm;
    float* x2s  = sm + 4224;
    float* cgs  = sm + 8448;
    float* Ws   = sm + 9780;
    ull*   cats = (ull*)(sm + 10356);

    const int item = blockIdx.x >> 4;          // 0..110 (l, pair)
    const int b0   = (blockIdx.x & 15) << 4;   // batch tile start

    // decode work item: l ordered 5,4,3,2,1,0 (big work first)
    int l = 0, l1 = 0, l2 = 0, pidx = 0;
    {
        int cur = 0;
        bool done = false;
        for (int oi = 0; oi < 6 && !done; ++oi) {
            int L = 5 - oi;
            int pi = 0;
            for (int a = 0; a <= 5 && !done; ++a) {
                for (int b2 = 0; b2 <= 5; ++b2) {
                    int dd = a - b2; if (dd < 0) dd = -dd;
                    if (dd <= L && L <= a + b2) {
                        if (cur == item) { l = L; l1 = a; l2 = b2; pidx = pi; done = true; break; }
                        ++cur; ++pi;
                    }
                }
            }
        }
    }

    const int n1 = 2 * l1 + 1, n2 = 2 * l2 + 1, n = 2 * l + 1;
    int KIN, moff;
    switch (l) {
        case 0: KIN = 3456;  moff = 0;  break;
        case 1: KIN = 8640;  moff = 1;  break;
        case 2: KIN = 12096; moff = 4;  break;
        case 3: KIN = 13824; moff = 9;  break;
        case 4: KIN = 13824; moff = 16; break;
        default: KIN = 12096; moff = 25; break;
    }
    const float* Xa = pick6(X0, X1, X2, X3, X4, X5, l1);
    const float* Xb = pick6(X0, X1, X2, X3, X4, X5, l2);
    const float* Wl = pick6(W0, W1, W2, W3, W4, W5, l);
    const int koff = pidx * 576;
    const int tid = threadIdx.x;

    // load x tiles: global (b,c,m) -> smem [c][m][b16]
    for (int i = tid; i < 16 * 24 * n1; i += BLK) {
        int b = i / (24 * n1);
        int r = i - b * 24 * n1;
        int c = r / n1;
        int m1 = r - c * n1;
        x1s[(c * 11 + m1) * 16 + b] = Xa[(b0 + b) * 24 * n1 + r];
    }
    for (int i = tid; i < 16 * 24 * n2; i += BLK) {
        int b = i / (24 * n2);
        int r = i - b * 24 * n2;
        int c = r / n2;
        int m2 = r - c * n2;
        x2s[(c * 11 + m2) * 16 + b] = Xb[(b0 + b) * 24 * n2 + r];
    }
    const float* cgp = cg + ((l1 * 6 + l2) * 6 + l) * 1331;
    for (int i = tid; i < n * 121; i += BLK) cgs[i] = cgp[i];
    __syncthreads();

    const int cbase = l1 + l2 - l;
    switch (l) {
        case 0: run_pair<1>(x1s, x2s, cgs, Ws, cats, Wl, KIN, koff, n1, n2, cbase, out, b0, moff); break;
        case 1: run_pair<3>(x1s, x2s, cgs, Ws, cats, Wl, KIN, koff, n1, n2, cbase, out, b0, moff); break;
        case 2: run_pair<5>(x1s, x2s, cgs, Ws, cats, Wl, KIN, koff, n1, n2, cbase, out, b0, moff); break;
        case 3: run_pair<7>(x1s, x2s, cgs, Ws, cats, Wl, KIN, koff, n1, n2, cbase, out, b0, moff); break;
        case 4: run_pair<9>(x1s, x2s, cgs, Ws, cats, Wl, KIN, koff, n1, n2, cbase, out, b0, moff); break;
        default: run_pair<11>(x1s, x2s, cgs, Ws, cats, Wl, KIN, koff, n1, n2, cbase, out, b0, moff); break;
    }
}

__global__ void zero_out_kernel(float* __restrict__ o, int nTot) {
    int i = blockIdx.x * 256 + threadIdx.x;
    if (i < nTot) o[i] = 0.f;
}

extern "C" void kernel_launch(void* const* d_in, const int* in_sizes, int n_in,
                              void* d_out, int out_size)
{
    const float* X[6];
    const float* W[6];
    for (int i = 0; i < 6; ++i) X[i] = (const float*)d_in[i];
    for (int i = 0; i < 6; ++i) W[i] = (const float*)d_in[6 + i];
    const float* cg = (const float*)d_in[12];
    float* out = (float*)d_out;

    const int nTot = 256 * 32 * 36;  // 294912
    zero_out_kernel<<<(nTot + 255) / 256, 256>>>(out, nTot);

    cudaFuncSetAttribute(cg_main, cudaFuncAttributeMaxDynamicSharedMemorySize, SMEM_BYTES);
    cg_main<<<111 * 16, BLK, SMEM_BYTES>>>(
        X[0], X[1], X[2], X[3], X[4], X[5],
        W[0], W[1], W[2], W[3], W[4], W[5],
        cg, out);
}